// round 17
// baseline (speedup 1.0000x reference)
// v10: 128-query attention blocks (halved K/V L2 traffic), attn-first block order.
#include <cuda_runtime.h>
#include <math.h>

#define PP 3136
#define CC 256
#define BB 2
#define WX 56
#define EPS 1e-5f
#define SLOPE 0.01f

#define BUFN ((long)BB * CC * PP)
__device__ float g_buf[7 * BB * CC * PP];

#define MM_STAGE_F 3712
#define MM_SMEM (4 * MM_STAGE_F * 4)   // 59392 bytes
#define FUSED_SMEM 55296

__device__ __forceinline__ unsigned f2tf(float f) {
    unsigned u;
    asm("cvt.rna.tf32.f32 %0, %1;" : "=r"(u) : "f"(f));
    return u;
}
__device__ __forceinline__ float f2tff(float f) { return __uint_as_float(f2tf(f)); }

__device__ __forceinline__ float ex2f(float x) {
    float r;
    asm("ex2.approx.f32 %0, %1;" : "=f"(r) : "f"(x));
    return r;
}

__device__ __forceinline__ void mma8(float* c, const unsigned* a, unsigned b0, unsigned b1) {
    asm volatile(
        "mma.sync.aligned.m16n8k8.row.col.f32.tf32.tf32.f32 "
        "{%0,%1,%2,%3}, {%4,%5,%6,%7}, {%8,%9}, {%0,%1,%2,%3};"
        : "+f"(c[0]), "+f"(c[1]), "+f"(c[2]), "+f"(c[3])
        : "r"(a[0]), "r"(a[1]), "r"(a[2]), "r"(a[3]), "r"(b0), "r"(b1));
}

// ---------------------------------------------------------------------------
// Attention unit, 128 queries (2 x 64-query subtiles sharing each K/V tile).
// 4 warps. cp.async double-buffered K/V, base-2 softmax, deferred l.
// has2=false for the tail singleton (q-tile 48). Uses 55296 B dsm.
// ---------------------------------------------------------------------------
__device__ __forceinline__ void attn2_body(
    const float* __restrict__ Q, const float* __restrict__ K,
    const float* __restrict__ V, float* __restrict__ out,
    int q0, bool has2, int b, int h, float* dsm)
{
    float* KB0 = dsm;
    float* KB1 = dsm + 2304;
    float* VB0 = dsm + 4608;
    float* VB1 = dsm + 6912;
    float* Ppool = dsm + 9216;

    const int tid = threadIdx.x, lane = tid & 31, w = tid >> 5;
    const long base = ((long)b * CC + h * 32) * PP;
    const float* qp = Q + base;
    const float* kp = K + base;
    const float* vp = V + base;
    const float SC = 0.17677669529663687f * 1.4426950408889634f;

    const int ld_d = tid >> 4, ld_k4 = (tid & 15) * 4;

    auto issue_tile = [&](int kb, float* Kd, float* Vd) {
#pragma unroll
        for (int j = 0; j < 4; j++) {
            int d = ld_d + j * 8;
            unsigned ks = (unsigned)__cvta_generic_to_shared(Kd + d * 72 + ld_k4);
            unsigned vs = (unsigned)__cvta_generic_to_shared(Vd + d * 72 + ld_k4);
            const float* kg = kp + (long)d * PP + kb + ld_k4;
            const float* vg = vp + (long)d * PP + kb + ld_k4;
            asm volatile("cp.async.ca.shared.global [%0], [%1], 16;" :: "r"(ks), "l"(kg));
            asm volatile("cp.async.ca.shared.global [%0], [%1], 16;" :: "r"(vs), "l"(vg));
        }
        asm volatile("cp.async.commit_group;" ::: "memory");
    };

    issue_tile(0, KB0, VB0);

    // ---- load Q subtile fragments (two passes through Ppool-as-Qs) ----
    unsigned af[2][4][4];
    float* Qs = Ppool;
    const int rr = w * 16 + (lane >> 2);
    const int cc = lane & 3;
#pragma unroll
    for (int sub = 0; sub < 2; sub++) {
        if (sub == 1 && !has2) {
#pragma unroll
            for (int kc = 0; kc < 4; kc++)
#pragma unroll
                for (int j = 0; j < 4; j++) af[1][kc][j] = af[0][kc][j];
            break;
        }
        int qb = q0 + sub * 64;
        __syncthreads();   // prior extraction (sub 0) done before overwrite
        for (int i = tid; i < 512; i += 128) {
            int d = i >> 4, q4 = (i & 15) * 4;
            float4 v4 = *(const float4*)(qp + (long)d * PP + qb + q4);
            Qs[(q4 + 0) * 36 + d] = f2tff(v4.x * SC);
            Qs[(q4 + 1) * 36 + d] = f2tff(v4.y * SC);
            Qs[(q4 + 2) * 36 + d] = f2tff(v4.z * SC);
            Qs[(q4 + 3) * 36 + d] = f2tff(v4.w * SC);
        }
        __syncthreads();
#pragma unroll
        for (int kc = 0; kc < 4; kc++) {
            af[sub][kc][0] = __float_as_uint(Qs[rr * 36 + kc * 8 + cc]);
            af[sub][kc][1] = __float_as_uint(Qs[(rr + 8) * 36 + kc * 8 + cc]);
            af[sub][kc][2] = __float_as_uint(Qs[rr * 36 + kc * 8 + cc + 4]);
            af[sub][kc][3] = __float_as_uint(Qs[(rr + 8) * 36 + kc * 8 + cc + 4]);
        }
    }
    __syncthreads();   // Ppool free for P use

    float m0[2] = {-1e30f, -1e30f}, m1[2] = {-1e30f, -1e30f};
    float l0[2] = {0.f, 0.f}, l1[2] = {0.f, 0.f};
    float o[2][4][4];
#pragma unroll
    for (int sub = 0; sub < 2; sub++)
#pragma unroll
        for (int nt = 0; nt < 4; nt++)
#pragma unroll
            for (int j = 0; j < 4; j++) o[sub][nt][j] = 0.f;

    float* Pw = Ppool + w * 16 * 72;
    const int lq = lane >> 2;
    const int lr = lane & 3;
    const int cbase = 2 * ((2 * lr) & 3) + (lr >> 1);
    const int nsub = has2 ? 2 : 1;

    for (int kt = 0; kt < 49; kt++) {
        asm volatile("cp.async.wait_group 0;" ::: "memory");
        __syncthreads();
        if (kt < 48) {
            int nb = (kt + 1) & 1;
            issue_tile((kt + 1) * 64, nb ? KB1 : KB0, nb ? VB1 : VB0);
        }
        const float* Ksb = (kt & 1) ? KB1 : KB0;
        const float* Vsb = (kt & 1) ? VB1 : VB0;

        for (int sub = 0; sub < nsub; sub++) {
            float s[8][4];
#pragma unroll
            for (int nt = 0; nt < 8; nt++)
#pragma unroll
                for (int j = 0; j < 4; j++) s[nt][j] = 0.f;
#pragma unroll
            for (int kc = 0; kc < 4; kc++) {
#pragma unroll
                for (int nt = 0; nt < 8; nt++) {
                    unsigned b0 = __float_as_uint(Ksb[(kc * 8 + lr) * 72 + nt * 8 + lq]);
                    unsigned b1 = __float_as_uint(Ksb[(kc * 8 + lr + 4) * 72 + nt * 8 + lq]);
                    mma8(s[nt], af[sub][kc], b0, b1);
                }
            }

            float mx0 = s[0][0], mx1 = s[0][2];
#pragma unroll
            for (int nt = 0; nt < 8; nt++) {
                mx0 = fmaxf(mx0, fmaxf(s[nt][0], s[nt][1]));
                mx1 = fmaxf(mx1, fmaxf(s[nt][2], s[nt][3]));
            }
            mx0 = fmaxf(mx0, __shfl_xor_sync(0xffffffffu, mx0, 1));
            mx0 = fmaxf(mx0, __shfl_xor_sync(0xffffffffu, mx0, 2));
            mx1 = fmaxf(mx1, __shfl_xor_sync(0xffffffffu, mx1, 1));
            mx1 = fmaxf(mx1, __shfl_xor_sync(0xffffffffu, mx1, 2));
            float nm0 = fmaxf(m0[sub], mx0), nm1 = fmaxf(m1[sub], mx1);
            float a0 = ex2f(m0[sub] - nm0), a1 = ex2f(m1[sub] - nm1);
            m0[sub] = nm0; m1[sub] = nm1;

            float ps0 = 0.f, ps1 = 0.f;
#pragma unroll
            for (int nt = 0; nt < 8; nt++) {
                s[nt][0] = ex2f(s[nt][0] - nm0); ps0 += s[nt][0];
                s[nt][1] = ex2f(s[nt][1] - nm0); ps0 += s[nt][1];
                s[nt][2] = ex2f(s[nt][2] - nm1); ps1 += s[nt][2];
                s[nt][3] = ex2f(s[nt][3] - nm1); ps1 += s[nt][3];
            }
            l0[sub] = l0[sub] * a0 + ps0;
            l1[sub] = l1[sub] * a1 + ps1;
#pragma unroll
            for (int nt = 0; nt < 4; nt++) {
                o[sub][nt][0] *= a0; o[sub][nt][1] *= a0;
                o[sub][nt][2] *= a1; o[sub][nt][3] *= a1;
            }

            __syncwarp();
#pragma unroll
            for (int nt = 0; nt < 8; nt++) {
                float* pr = Pw + lq * 72 + nt * 8 + cbase;
                pr[0] = f2tff(s[nt][0]);
                pr[2] = f2tff(s[nt][1]);
                float* pr2 = pr + 8 * 72;
                pr2[0] = f2tff(s[nt][2]);
                pr2[2] = f2tff(s[nt][3]);
            }
            __syncwarp();

#pragma unroll
            for (int kc = 0; kc < 8; kc++) {
                unsigned pa[4];
                float2 plo = *(const float2*)(Pw + lq * 72 + kc * 8 + 2 * lr);
                float2 phi = *(const float2*)(Pw + (lq + 8) * 72 + kc * 8 + 2 * lr);
                pa[0] = __float_as_uint(plo.x); pa[1] = __float_as_uint(phi.x);
                pa[2] = __float_as_uint(plo.y); pa[3] = __float_as_uint(phi.y);
#pragma unroll
                for (int nt = 0; nt < 4; nt++) {
                    unsigned b0 = __float_as_uint(Vsb[(nt * 8 + lq) * 72 + kc * 8 + lr]);
                    unsigned b1 = __float_as_uint(Vsb[(nt * 8 + lq) * 72 + kc * 8 + lr + 4]);
                    mma8(o[sub][nt], pa, b0, b1);
                }
            }
        }
    }

    float* op = out + (long)b * (2 * CC * PP) + (long)(h * 32) * PP;
#pragma unroll
    for (int sub = 0; sub < 2; sub++) {
        if (sub == 1 && !has2) break;
        float la = l0[sub] + __shfl_xor_sync(0xffffffffu, l0[sub], 1);
        la += __shfl_xor_sync(0xffffffffu, la, 2);
        float lb = l1[sub] + __shfl_xor_sync(0xffffffffu, l1[sub], 1);
        lb += __shfl_xor_sync(0xffffffffu, lb, 2);
        float inv0 = 1.f / la, inv1 = 1.f / lb;
        int qr = q0 + sub * 64 + w * 16 + lq;
#pragma unroll
        for (int nt = 0; nt < 4; nt++) {
            int d = nt * 8 + lr * 2;
            op[(long)d * PP + qr]           = o[sub][nt][0] * inv0;
            op[(long)(d + 1) * PP + qr]     = o[sub][nt][1] * inv0;
            op[(long)d * PP + qr + 8]       = o[sub][nt][2] * inv1;
            op[(long)(d + 1) * PP + qr + 8] = o[sub][nt][3] * inv1;
        }
    }
}

// ---------------------------------------------------------------------------
// Conv unit (device fn): Ks 3x3 implicit GEMM, BM=64, BN=64, 128 threads,
// register double-buffered, K=2304 (same k order -> bit-identical sums).
// Epilogue: out = (acc + bias[o]) * Qbuf. Uses 9216 B of dsm.
// ---------------------------------------------------------------------------
__device__ __forceinline__ void conv64_body(
    const float* __restrict__ W, const float* __restrict__ X,
    float* __restrict__ out, const float* __restrict__ bias,
    const float* __restrict__ aux, int b, int o0, int p0, float* dsm)
{
    float* As = dsm;
    float* Bs = dsm + 16 * 72;
    const int KK = CC * 9;
    const float* Xb = X + (long)b * CC * PP;
    const int tid = threadIdx.x, lane = tid & 31, w = tid >> 5;
    const int mw = (w & 1) * 32, nw = (w >> 1) * 32;
    const int r = lane >> 2, cA = lane & 3;

    float acc[2][4][4];
#pragma unroll
    for (int mt = 0; mt < 2; mt++)
#pragma unroll
        for (int nt = 0; nt < 4; nt++)
#pragma unroll
            for (int j = 0; j < 4; j++) acc[mt][nt][j] = 0.f;

    const int arow = tid >> 1, aoff = (tid & 1) * 8;
    const int brow = tid >> 3, bn0 = (tid & 7) * 8;

    float ast[8], bst[8];
    auto load_slab = [&](int k0) {
        const float* wp = W + (long)(o0 + arow) * KK + k0 + aoff;
        float4 wa = *(const float4*)(wp);
        float4 wb = *(const float4*)(wp + 4);
        ast[0] = f2tff(wa.x); ast[1] = f2tff(wa.y);
        ast[2] = f2tff(wa.z); ast[3] = f2tff(wa.w);
        ast[4] = f2tff(wb.x); ast[5] = f2tff(wb.y);
        ast[6] = f2tff(wb.z); ast[7] = f2tff(wb.w);
        int kk = k0 + brow;
        int c = kk / 9, t = kk - c * 9;
        int dy = t / 3 - 1, dx = t - (t / 3) * 3 - 1;
        const float* Xc = Xb + (long)c * PP;
#pragma unroll
        for (int q = 0; q < 8; q++) {
            int p = p0 + bn0 + q;
            int y = p / WX, x = p - y * WX;
            int yy = y + dy, xx = x + dx;
            float v = 0.f;
            if ((unsigned)yy < WX && (unsigned)xx < WX)
                v = Xc[yy * WX + xx];
            bst[q] = f2tff(v);
        }
    };

    load_slab(0);
    for (int k0 = 0; k0 < KK; k0 += 16) {
        __syncthreads();
#pragma unroll
        for (int j = 0; j < 8; j++) As[(aoff + j) * 72 + arow] = ast[j];
#pragma unroll
        for (int q = 0; q < 8; q++) Bs[brow * 72 + bn0 + q] = bst[q];
        __syncthreads();
        if (k0 + 16 < KK) load_slab(k0 + 16);
#pragma unroll
        for (int kc = 0; kc < 2; kc++) {
            unsigned af[2][4];
#pragma unroll
            for (int mt = 0; mt < 2; mt++) {
                int mb = mw + mt * 16 + r;
                af[mt][0] = __float_as_uint(As[(kc * 8 + cA) * 72 + mb]);
                af[mt][1] = __float_as_uint(As[(kc * 8 + cA) * 72 + mb + 8]);
                af[mt][2] = __float_as_uint(As[(kc * 8 + cA + 4) * 72 + mb]);
                af[mt][3] = __float_as_uint(As[(kc * 8 + cA + 4) * 72 + mb + 8]);
            }
#pragma unroll
            for (int nt = 0; nt < 4; nt++) {
                unsigned b0 = __float_as_uint(Bs[(kc * 8 + cA) * 72 + nw + nt * 8 + r]);
                unsigned b1 = __float_as_uint(Bs[(kc * 8 + cA + 4) * 72 + nw + nt * 8 + r]);
                mma8(acc[0][nt], af[0], b0, b1);
                mma8(acc[1][nt], af[1], b0, b1);
            }
        }
    }

#pragma unroll
    for (int mt = 0; mt < 2; mt++) {
        int o_lo = o0 + mw + mt * 16 + r;
        int o_hi = o_lo + 8;
        float bi_lo = bias[o_lo], bi_hi = bias[o_hi];
#pragma unroll
        for (int nt = 0; nt < 4; nt++) {
            int p = p0 + nw + nt * 8 + 2 * cA;
            long oi_lo = (long)b * CC * PP + (long)o_lo * PP + p;
            long oi_hi = (long)b * CC * PP + (long)o_hi * PP + p;
            float2 ql = *(const float2*)(aux + oi_lo);
            float2 qh = *(const float2*)(aux + oi_hi);
            float2 rl, rh;
            rl.x = (acc[mt][nt][0] + bi_lo) * ql.x; rl.y = (acc[mt][nt][1] + bi_lo) * ql.y;
            rh.x = (acc[mt][nt][2] + bi_hi) * qh.x; rh.y = (acc[mt][nt][3] + bi_hi) * qh.y;
            *(float2*)(out + oi_lo) = rl;
            *(float2*)(out + oi_hi) = rh;
        }
    }
}

// ---------------------------------------------------------------------------
// Fused mega-kernel: 792 blocks x 128 threads.
// bx < 400: attention (25 units/bh x 16 bh); bx >= 400: conv (392 blocks).
// ---------------------------------------------------------------------------
__global__ void __launch_bounds__(128)
fused_attn_conv_k(const float* __restrict__ Q, const float* __restrict__ K,
                  const float* __restrict__ V, float* __restrict__ out,
                  const float* __restrict__ ksw, const float* __restrict__ x,
                  const float* __restrict__ ksb, float* __restrict__ QKs)
{
    extern __shared__ float dsm[];
    const int bx = blockIdx.x;
    if (bx < 400) {
        int u = bx % 25, bh = bx / 25;
        attn2_body(Q, K, V, out, u * 128, u < 24, bh >> 3, bh & 7, dsm);
    } else {
        int ci = bx - 400;                  // 0..391
        int ptile = ci % 49;
        int rest = ci / 49;
        int otile = rest & 3, b = rest >> 2;
        conv64_body(ksw, x, QKs, ksb, Q, b, otile * 64, ptile * 64, dsm);
    }
}

// ---------------------------------------------------------------------------
// Pipelined dense tf32 GEMM (unchanged from v8).
// MODE 0: +bias | 1: aux*sigmoid(+bias) | 2: BN+leaky | 4: +bias tf32-rounded
// ---------------------------------------------------------------------------
template <int MODE>
__device__ __forceinline__ void mmp_body(
    const float* __restrict__ W, const float* __restrict__ X,
    float* __restrict__ out,
    const float* __restrict__ bias, const float* __restrict__ aux,
    const float* __restrict__ g, const float* __restrict__ bt,
    const float* __restrict__ mn, const float* __restrict__ vr,
    long outB, int b, int o0, int p0, float* sm)
{
    const float* Xb = X + (long)b * CC * PP;
    const int tid = threadIdx.x, lane = tid & 31, w = tid >> 5;
    const int wm = w & 3, wn = w >> 2;
    const int mw = wm * 32, nw = wn * 32;
    const int r = lane >> 2, cA = lane & 3;

    const int arow = tid >> 1, aoff = (tid & 1) * 8;
    const int brow = tid >> 4, boff = (tid & 15) * 4;

    auto issue_slab = [&](int s) {
        if (s < 16) {
            float* Asm = sm + (s & 3) * MM_STAGE_F;
            float* Bsm = Asm + 2560;
            const float* wsrc = W + (long)(o0 + arow) * CC + s * 16 + aoff;
            unsigned ad = (unsigned)__cvta_generic_to_shared(Asm + arow * 20 + aoff);
            asm volatile("cp.async.cg.shared.global [%0], [%1], 16;" :: "r"(ad), "l"(wsrc));
            asm volatile("cp.async.cg.shared.global [%0], [%1], 16;" :: "r"(ad + 16u), "l"(wsrc + 4));
            const float* xsrc = Xb + (long)(s * 16 + brow) * PP + p0 + boff;
            unsigned bd = (unsigned)__cvta_generic_to_shared(Bsm + brow * 72 + boff);
            asm volatile("cp.async.cg.shared.global [%0], [%1], 16;" :: "r"(bd), "l"(xsrc));
        }
        asm volatile("cp.async.commit_group;" ::: "memory");
    };

    issue_slab(0); issue_slab(1); issue_slab(2);

    float acc[2][4][4];
#pragma unroll
    for (int mt = 0; mt < 2; mt++)
#pragma unroll
        for (int nt = 0; nt < 4; nt++)
#pragma unroll
            for (int j = 0; j < 4; j++) acc[mt][nt][j] = 0.f;

    for (int s = 0; s < 16; s++) {
        asm volatile("cp.async.wait_group 2;" ::: "memory");
        __syncthreads();
        issue_slab(s + 3);
        const float* Asm = sm + (s & 3) * MM_STAGE_F;
        const float* Bsm = Asm + 2560;
#pragma unroll
        for (int kc = 0; kc < 2; kc++) {
            unsigned af[2][4];
#pragma unroll
            for (int mt = 0; mt < 2; mt++) {
                int mb = mw + mt * 16 + r;
                af[mt][0] = f2tf(Asm[mb * 20 + kc * 8 + cA]);
                af[mt][1] = f2tf(Asm[(mb + 8) * 20 + kc * 8 + cA]);
                af[mt][2] = f2tf(Asm[mb * 20 + kc * 8 + cA + 4]);
                af[mt][3] = f2tf(Asm[(mb + 8) * 20 + kc * 8 + cA + 4]);
            }
#pragma unroll
            for (int nt = 0; nt < 4; nt++) {
                unsigned b0 = f2tf(Bsm[(kc * 8 + cA) * 72 + nw + nt * 8 + r]);
                unsigned b1 = f2tf(Bsm[(kc * 8 + cA + 4) * 72 + nw + nt * 8 + r]);
                mma8(acc[0][nt], af[0], b0, b1);
                mma8(acc[1][nt], af[1], b0, b1);
            }
        }
    }

#pragma unroll
    for (int mt = 0; mt < 2; mt++) {
        int o_lo = o0 + mw + mt * 16 + r;
        int o_hi = o_lo + 8;
        float bi_lo = 0.f, bi_hi = 0.f, sc_lo = 0.f, sc_hi = 0.f, sb_lo = 0.f, sb_hi = 0.f;
        if (MODE != 2) { bi_lo = bias[o_lo]; bi_hi = bias[o_hi]; }
        if (MODE == 2) {
            sc_lo = g[o_lo] * rsqrtf(vr[o_lo] + EPS); sb_lo = bt[o_lo] - mn[o_lo] * sc_lo;
            sc_hi = g[o_hi] * rsqrtf(vr[o_hi] + EPS); sb_hi = bt[o_hi] - mn[o_hi] * sc_hi;
        }
#pragma unroll
        for (int nt = 0; nt < 4; nt++) {
            int p = p0 + nw + nt * 8 + 2 * cA;
            long oi_lo = (long)b * outB + (long)o_lo * PP + p;
            long oi_hi = (long)b * outB + (long)o_hi * PP + p;
            float2 rl, rh;
            float a0 = acc[mt][nt][0], a1 = acc[mt][nt][1];
            float a2 = acc[mt][nt][2], a3 = acc[mt][nt][3];
            if (MODE == 0) {
                rl.x = a0 + bi_lo; rl.y = a1 + bi_lo;
                rh.x = a2 + bi_hi; rh.y = a3 + bi_hi;
            } else if (MODE == 4) {
                rl.x = f2tff(a0 + bi_lo); rl.y = f2tff(a1 + bi_lo);
                rh.x = f2tff(a2 + bi_hi); rh.y = f2tff(a3 + bi_hi);
            } else if (MODE == 1) {
                long ai_lo = (long)b * CC * PP + (long)o_lo * PP + p;
                long ai_hi = (long)b * CC * PP + (long)o_hi * PP + p;
                float2 vl = *(const float2*)(aux + ai_lo);
                float2 vh = *(const float2*)(aux + ai_hi);
                rl.x = vl.x / (1.f + __expf(-(a0 + bi_lo)));
                rl.y = vl.y / (1.f + __expf(-(a1 + bi_lo)));
                rh.x = vh.x / (1.f + __expf(-(a2 + bi_hi)));
                rh.y = vh.y / (1.f + __expf(-(a3 + bi_hi)));
            } else {
                float t0 = a0 * sc_lo + sb_lo, t1 = a1 * sc_lo + sb_lo;
                float t2 = a2 * sc_hi + sb_hi, t3 = a3 * sc_hi + sb_hi;
                rl.x = t0 > 0.f ? t0 : SLOPE * t0; rl.y = t1 > 0.f ? t1 : SLOPE * t1;
                rh.x = t2 > 0.f ? t2 : SLOPE * t2; rh.y = t3 > 0.f ? t3 : SLOPE * t3;
            }
            *(float2*)(out + oi_lo) = rl;
            *(float2*)(out + oi_hi) = rh;
        }
    }
}

template <int MODE>
__global__ void __launch_bounds__(256)
mmp_k(const float* __restrict__ W, const float* __restrict__ X,
      float* __restrict__ out,
      const float* __restrict__ bias, const float* __restrict__ aux,
      const float* __restrict__ g, const float* __restrict__ bt,
      const float* __restrict__ mn, const float* __restrict__ vr,
      long outB)
{
    extern __shared__ float sm[];
    mmp_body<MODE>(W, X, out, bias, aux, g, bt, mn, vr, outB,
                   blockIdx.z, blockIdx.y * 128, blockIdx.x * 64, sm);
}

// Merged Q/K/V projection (pipelined, MODE 4 tf32-rounded outputs).
__global__ void __launch_bounds__(256)
qkvp_k(const float* __restrict__ qw, const float* __restrict__ qb,
       const float* __restrict__ kw, const float* __restrict__ kb,
       const float* __restrict__ vw, const float* __restrict__ vb,
       const float* __restrict__ X,
       float* __restrict__ Q, float* __restrict__ Kb, float* __restrict__ Vb)
{
    extern __shared__ float sm[];
    const int y = blockIdx.y;
    const int sel = y >> 1;
    const float* W    = sel == 0 ? qw : (sel == 1 ? kw : vw);
    const float* bias = sel == 0 ? qb : (sel == 1 ? kb : vb);
    float* out        = sel == 0 ? Q  : (sel == 1 ? Kb : Vb);
    mmp_body<4>(W, X, out, bias, nullptr, nullptr, nullptr, nullptr, nullptr,
                (long)CC * PP, blockIdx.z, (y & 1) * 128, blockIdx.x * 64, sm);
}

// ---------------------------------------------------------------------------
// Depthwise 3x3 conv + BN1 + leaky ReLU (elementwise).
// ---------------------------------------------------------------------------
__global__ void __launch_bounds__(256)
dw_bn_lrelu_k(const float* __restrict__ in, const float* __restrict__ w9,
              const float* __restrict__ g, const float* __restrict__ bt,
              const float* __restrict__ mn, const float* __restrict__ vv,
              float* __restrict__ out)
{
    long idx = (long)blockIdx.x * 256 + threadIdx.x;
    if (idx >= (long)BB * CC * PP) return;
    int p = (int)(idx % PP);
    int c = (int)((idx / PP) % CC);
    int y = p / WX, x = p - y * WX;
    const float* ip = in + (idx - p);
    const float* wc = w9 + c * 9;
    float s = 0.f;
#pragma unroll
    for (int dy = -1; dy <= 1; dy++) {
        int yy = y + dy;
        if ((unsigned)yy >= WX) continue;
#pragma unroll
        for (int dx = -1; dx <= 1; dx++) {
            int xx = x + dx;
            if ((unsigned)xx >= WX) continue;
            s += wc[(dy + 1) * 3 + (dx + 1)] * ip[yy * WX + xx];
        }
    }
    float sc = g[c] * rsqrtf(vv[c] + EPS);
    float t = (s - mn[c]) * sc + bt[c];
    out[idx] = t > 0.f ? t : SLOPE * t;
}

// ---------------------------------------------------------------------------
extern "C" void kernel_launch(void* const* d_in, const int* in_sizes, int n_in,
                              void* d_out, int out_size)
{
    (void)in_sizes; (void)n_in; (void)out_size;
    const float* x    = (const float*)d_in[0];
    const float* qw   = (const float*)d_in[1];
    const float* qb   = (const float*)d_in[2];
    const float* kw   = (const float*)d_in[3];
    const float* kb   = (const float*)d_in[4];
    const float* vw   = (const float*)d_in[5];
    const float* vb   = (const float*)d_in[6];
    const float* ksw  = (const float*)d_in[7];
    const float* ksb  = (const float*)d_in[8];
    const float* sd1w = (const float*)d_in[9];
    const float* sd1b = (const float*)d_in[10];
    const float* sd2w = (const float*)d_in[11];
    const float* sd2b = (const float*)d_in[12];
    const float* dww  = (const float*)d_in[13];
    const float* bn1g = (const float*)d_in[14];
    const float* bn1b = (const float*)d_in[15];
    const float* bn1m = (const float*)d_in[16];
    const float* bn1v = (const float*)d_in[17];
    const float* pww  = (const float*)d_in[18];
    const float* bn2g = (const float*)d_in[19];
    const float* bn2b = (const float*)d_in[20];
    const float* bn2m = (const float*)d_in[21];
    const float* bn2v = (const float*)d_in[22];
    float* out = (float*)d_out;

    float* buf = nullptr;
    cudaGetSymbolAddress((void**)&buf, g_buf);
    float* Q   = buf + 0 * BUFN;
    float* Kb  = buf + 1 * BUFN;
    float* Vb  = buf + 2 * BUFN;
    float* QKs = buf + 3 * BUFN;
    float* VS  = buf + 4 * BUFN;
    float* Y   = buf + 5 * BUFN;
    float* Y2  = buf + 6 * BUFN;

    cudaFuncSetAttribute(fused_attn_conv_k, cudaFuncAttributeMaxDynamicSharedMemorySize, FUSED_SMEM);
    cudaFuncSetAttribute(qkvp_k,  cudaFuncAttributeMaxDynamicSharedMemorySize, MM_SMEM);
    cudaFuncSetAttribute(mmp_k<0>, cudaFuncAttributeMaxDynamicSharedMemorySize, MM_SMEM);
    cudaFuncSetAttribute(mmp_k<1>, cudaFuncAttributeMaxDynamicSharedMemorySize, MM_SMEM);
    cudaFuncSetAttribute(mmp_k<2>, cudaFuncAttributeMaxDynamicSharedMemorySize, MM_SMEM);

    dim3 gg(PP / 64, CC / 128, BB);   // (49, 2, 2)
    const long bs = (long)CC * PP;

    // merged Q, K, V projections (pipelined, tf32-rounded outputs)
    qkvp_k<<<dim3(PP / 64, 6, BB), 256, MM_SMEM>>>(qw, qb, kw, kb, vw, vb, x, Q, Kb, Vb);

    // fused: flash attention (128-query blocks, -> out[:, :256]) + Ks conv (-> QKs)
    fused_attn_conv_k<<<792, 128, FUSED_SMEM>>>(Q, Kb, Vb, out, ksw, x, ksb, QKs);

    // gate = sigmoid(sd1(QKs)); VS = V * gate
    mmp_k<1><<<gg, 256, MM_SMEM>>>(sd1w, QKs, VS, sd1b, Vb, nullptr, nullptr, nullptr, nullptr, bs);

    // depthwise 3x3 + BN1 + leaky -> Y
    long total = (long)BB * CC * PP;
    dw_bn_lrelu_k<<<(int)((total + 255) / 256), 256>>>(VS, dww, bn1g, bn1b, bn1m, bn1v, Y);

    // pointwise pww + BN2 + leaky -> Y2
    mmp_k<2><<<gg, 256, MM_SMEM>>>(pww, Y, Y2, nullptr, nullptr, bn2g, bn2b, bn2m, bn2v, bs);

    // sd2 projection -> out channels [256,512)
    mmp_k<0><<<gg, 256, MM_SMEM>>>(sd2w, Y2, out + (long)CC * PP, sd2b,
                                   nullptr, nullptr, nullptr, nullptr, nullptr, (long)2 * CC * PP);
}